// round 11
// baseline (speedup 1.0000x reference)
#include <cuda_runtime.h>
#include <math.h>

// YOLOv5-style loss, 2-kernel formulation with COMPENSATED winner accumulation.
//
// Winner scatter: g_winner[cell] holds (epoch<<47)|(entry+1)<<32|payload_bits.
// atomicMax implements last-update-wins (entry index decides within an epoch;
// stale epochs always lose).  Each successful update atomically adds
// (new_payload - prev_payload_of_this_epoch) to g_corr; the deltas telescope,
// so after the grid completes g_corr == sum of final winners' payloads.
// No passB sweep, no reset, no cleanup.  Finalize is a 1-thread kernel.
// Output: [loss, lbox, lobj, lcls]  (4 floats)

#define NA_   3
#define NC_   80
#define CH_   85
#define EPS_  1e-7f

// ---------------- device scratch ----------------
__device__ float g_box[3];
__device__ float g_cls[3];
__device__ float g_sp;            // weighted softplus sum
__device__ float g_corr;          // compensated winner payload sum
__device__ int   g_nv[3];
__device__ unsigned int g_epoch = 1u;   // bumped by finalize each call

#define MAX_BS 32
#define CELLS_PER_B (NA_*(80*80 + 40*40 + 20*20))   // 25200
__device__ unsigned long long g_winner[MAX_BS * CELLS_PER_B];

// ---------------- helpers ----------------
__device__ __forceinline__ float sigmoidf_(float x) {
    return 1.0f / (1.0f + __expf(-x));
}

__device__ __forceinline__ float softplus_bce0(float x) {
    return fmaxf(x, 0.0f) + log1pf(__expf(-fabsf(x)));
}

__device__ __forceinline__ float ciou_(float px, float py, float pw, float ph,
                                       float tx, float ty, float tw, float th) {
    float b1x1 = px - pw * 0.5f, b1x2 = px + pw * 0.5f;
    float b1y1 = py - ph * 0.5f, b1y2 = py + ph * 0.5f;
    float b2x1 = tx - tw * 0.5f, b2x2 = tx + tw * 0.5f;
    float b2y1 = ty - th * 0.5f, b2y2 = ty + th * 0.5f;

    float iw = fmaxf(fminf(b1x2, b2x2) - fmaxf(b1x1, b2x1), 0.0f);
    float ih = fmaxf(fminf(b1y2, b2y2) - fmaxf(b1y1, b2y1), 0.0f);
    float inter = iw * ih;

    float w1 = b1x2 - b1x1, h1 = b1y2 - b1y1 + EPS_;
    float w2 = b2x2 - b2x1, h2 = b2y2 - b2y1 + EPS_;
    float uni = w1 * h1 + w2 * h2 - inter + EPS_;
    float iou = inter / uni;

    float cw = fmaxf(b1x2, b2x2) - fminf(b1x1, b2x1);
    float ch = fmaxf(b1y2, b2y2) - fminf(b1y1, b2y1);
    float c2 = cw * cw + ch * ch + EPS_;

    float dx = (b2x1 + b2x2 - b1x1 - b1x2);
    float dy = (b2y1 + b2y2 - b1y1 - b1y2);
    float rho2 = (dx * dx + dy * dy) * 0.25f;

    float dv = atanf(w2 / h2) - atanf(w1 / h1);
    float v = (4.0f / (float)(M_PI * M_PI)) * dv * dv;
    float alpha = v / (v - iou + (1.0f + EPS_));

    return iou - (rho2 / c2 + v * alpha);
}

// ---------------- main kernel: passA + weighted obj softplus sweep ----------------
__global__ void __launch_bounds__(256)
k_main(const float* __restrict__ p0,
       const float* __restrict__ p1,
       const float* __restrict__ p2,
       const float* __restrict__ tg,
       const float* __restrict__ anc,
       int nt, int bs, int BA, int BOBJ) {
    int M = NA_ * nt;
    int Elvl = 5 * M;
    int Etot = 3 * Elvl;

    int c0 = bs * NA_ * 6400;
    int c1 = bs * NA_ * 1600;
    int c2 = bs * NA_ * 400;
    float w0 = 1.0f / (float)c0;
    float w1 = 1.0f / (float)c1;
    float w2 = 1.0f / (float)c2;

    if ((int)blockIdx.x < BA) {
        // ---------------- passA: one warp per candidate entry ----------------
        int warp = (blockIdx.x * blockDim.x + threadIdx.x) >> 5;
        int lane = threadIdx.x & 31;
        if (warp >= Etot) return;

        int lvl = warp / Elvl;
        int ein = warp - lvl * Elvl;
        int o = ein / M;
        int m = ein - o * M;
        int a = m / nt;
        int n = m - a * nt;

        int H = 80 >> lvl;
        int W = H;
        const float* pi = (lvl == 0) ? p0 : ((lvl == 1) ? p1 : p2);
        int woff = (lvl == 0) ? 0 : ((lvl == 1) ? c0 : c0 + c1);
        float wlvl = (lvl == 0) ? w0 : ((lvl == 1) ? w1 : w2);

        float gx = tg[n * 6 + 2] * (float)W;
        float gy = tg[n * 6 + 3] * (float)H;
        float gw = tg[n * 6 + 4] * (float)W;
        float gh = tg[n * 6 + 5] * (float)H;

        float aw = anc[(lvl * NA_ + a) * 2 + 0];
        float ah = anc[(lvl * NA_ + a) * 2 + 1];

        float rw = gw / aw, rh = gh / ah;
        float mr = fmaxf(fmaxf(rw, 1.0f / rw), fmaxf(rh, 1.0f / rh));
        bool m0 = mr < 4.0f;

        bool jmo;
        float offx = 0.0f, offy = 0.0f;
        switch (o) {
            case 0: jmo = true; break;
            case 1: jmo = ((gx - truncf(gx)) < 0.5f) && (gx > 1.0f); offx = 0.5f; break;
            case 2: jmo = ((gy - truncf(gy)) < 0.5f) && (gy > 1.0f); offy = 0.5f; break;
            case 3: { float gxi = (float)W - gx;
                      jmo = ((gxi - truncf(gxi)) < 0.5f) && (gxi > 1.0f); offx = -0.5f; } break;
            default:{ float gyi = (float)H - gy;
                      jmo = ((gyi - truncf(gyi)) < 0.5f) && (gyi > 1.0f); offy = -0.5f; } break;
        }

        if (!(jmo && m0)) return;

        int b = (int)tg[n * 6 + 0];
        int c = (int)tg[n * 6 + 1];

        int gi = (int)truncf(gx - offx); gi = min(max(gi, 0), W - 1);
        int gj = (int)truncf(gy - offy); gj = min(max(gj, 0), H - 1);

        const float* row = pi + (size_t)((((b * NA_ + a) * H + gj) * W + gi)) * CH_;

        float csum = 0.0f;
        #pragma unroll
        for (int it = 0; it < 3; it++) {
            int j = lane + it * 32;
            if (j < NC_) {
                float x = row[5 + j];
                float y = (j == c) ? 1.0f : 0.0f;
                csum += fmaxf(x, 0.0f) - x * y + log1pf(__expf(-fabsf(x)));
            }
        }
        #pragma unroll
        for (int s = 16; s; s >>= 1)
            csum += __shfl_down_sync(0xffffffffu, csum, s);

        if (lane == 0) {
            float q0 = row[0], q1 = row[1], q2 = row[2], q3 = row[3], q4 = row[4];
            float px = sigmoidf_(q0) * 2.0f - 0.5f;
            float py = sigmoidf_(q1) * 2.0f - 0.5f;
            float sw = sigmoidf_(q2) * 2.0f;  float pw = sw * sw * aw;
            float shh = sigmoidf_(q3) * 2.0f; float ph = shh * shh * ah;

            float tbx = gx - (float)gi;
            float tby = gy - (float)gj;

            float iou = ciou_(px, py, pw, ph, tbx, tby, gw, gh);

            atomicAdd(&g_box[lvl], 1.0f - iou);
            atomicAdd(&g_cls[lvl], csum);
            atomicAdd(&g_nv[lvl], 1);

            // compensated winner update
            int cell = woff + (((b * NA_ + a) * H + gj) * W + gi);
            unsigned int ep = g_epoch;
            float payload = wlvl * q4 * fmaxf(iou, 0.0f);
            unsigned long long tag =
                ((unsigned long long)ep << 47) |
                ((unsigned long long)(ein + 1) << 32) |
                (unsigned long long)__float_as_uint(payload);
            unsigned long long old = atomicMax(&g_winner[cell], tag);
            if (tag > old) {
                float prev = ((unsigned int)(old >> 47) == ep)
                           ? __uint_as_float((unsigned int)old) : 0.0f;
                atomicAdd(&g_corr, payload - prev);
            }
        }
    } else {
        // ---------------- weighted objectness softplus sweep ----------------
        __shared__ float sh[256];
        int bid = blockIdx.x - BA;
        int tid = threadIdx.x;
        int total = c0 + c1 + c2;

        float s = 0.0f;
        for (int i = bid * blockDim.x + tid; i < total; i += BOBJ * blockDim.x) {
            const float* pi; int local; float w;
            if (i < c0)            { pi = p0; local = i;            w = w0; }
            else if (i < c0 + c1)  { pi = p1; local = i - c0;       w = w1; }
            else                   { pi = p2; local = i - c0 - c1;  w = w2; }
            s += w * softplus_bce0(pi[(size_t)local * CH_ + 4]);
        }
        sh[tid] = s;
        __syncthreads();
        for (int st = 128; st; st >>= 1) {
            if (tid < st) sh[tid] += sh[tid + st];
            __syncthreads();
        }
        if (tid == 0) atomicAdd(&g_sp, sh[0]);
    }
}

// ---------------- finalize: 1 thread ----------------
__global__ void k_fin(float* __restrict__ out, int bs) {
    float lbox = 0.0f, lcls = 0.0f;
    #pragma unroll
    for (int i = 0; i < 3; i++) {
        float nv = fmaxf((float)g_nv[i], 1.0f);
        lbox += g_box[i] / nv;
        lcls += g_cls[i] / (nv * (float)NC_);
        g_box[i] = 0.0f; g_cls[i] = 0.0f; g_nv[i] = 0;
    }
    float lobj = g_sp - g_corr;
    g_sp = 0.0f; g_corr = 0.0f;
    lbox *= 0.05f;   // BOX_GAIN
    lcls *= 0.5f;    // CLS_GAIN
    float loss = (lbox + lobj + lcls) * (float)bs;
    out[0] = loss;
    out[1] = lbox;
    out[2] = lobj;
    out[3] = lcls;
    g_epoch = g_epoch + 1u;   // invalidate this call's winner tags
}

// ---------------- launch ----------------
extern "C" void kernel_launch(void* const* d_in, const int* in_sizes, int n_in,
                              void* d_out, int out_size) {
    const float* p0  = (const float*)d_in[0];
    const float* p1  = (const float*)d_in[1];
    const float* p2  = (const float*)d_in[2];
    const float* tg  = (const float*)d_in[3];
    const float* anc = (const float*)d_in[4];
    float* out = (float*)d_out;

    int bs = in_sizes[0] / (NA_ * 80 * 80 * CH_);
    int nt = in_sizes[3] / 6;

    int Etot = 3 * 5 * NA_ * nt;
    int BA = (Etot * 32 + 255) / 256;   // warp-per-entry blocks
    int BOBJ = 512;                     // obj sweep blocks

    k_main<<<BA + BOBJ, 256>>>(p0, p1, p2, tg, anc, nt, bs, BA, BOBJ);
    k_fin<<<1, 1>>>(out, bs);
}

// round 13
// speedup vs baseline: 1.3110x; 1.3110x over previous
#include <cuda_runtime.h>
#include <math.h>

// YOLOv5-style loss, 2-kernel formulation, compensated winner accumulation +
// block-level scalar reduction.
// Output: [loss, lbox, lobj, lcls]  (4 floats)

#define NA_   3
#define NC_   80
#define CH_   85
#define EPS_  1e-7f

// ---------------- device scratch ----------------
__device__ float g_box[3];
__device__ float g_cls[3];
__device__ float g_sp;            // weighted softplus sum
__device__ float g_corr;          // compensated winner payload sum
__device__ int   g_nv[3];
__device__ unsigned int g_epoch = 1u;   // bumped by finalize each call

#define MAX_BS 32
#define CELLS_PER_B (NA_*(80*80 + 40*40 + 20*20))   // 25200
__device__ unsigned long long g_winner[MAX_BS * CELLS_PER_B];

// ---------------- helpers ----------------
__device__ __forceinline__ float sigmoidf_(float x) {
    return 1.0f / (1.0f + __expf(-x));
}

__device__ __forceinline__ float softplus_bce0(float x) {
    return fmaxf(x, 0.0f) + log1pf(__expf(-fabsf(x)));
}

__device__ __forceinline__ float ciou_(float px, float py, float pw, float ph,
                                       float tx, float ty, float tw, float th) {
    float b1x1 = px - pw * 0.5f, b1x2 = px + pw * 0.5f;
    float b1y1 = py - ph * 0.5f, b1y2 = py + ph * 0.5f;
    float b2x1 = tx - tw * 0.5f, b2x2 = tx + tw * 0.5f;
    float b2y1 = ty - th * 0.5f, b2y2 = ty + th * 0.5f;

    float iw = fmaxf(fminf(b1x2, b2x2) - fmaxf(b1x1, b2x1), 0.0f);
    float ih = fmaxf(fminf(b1y2, b2y2) - fmaxf(b1y1, b2y1), 0.0f);
    float inter = iw * ih;

    float w1 = b1x2 - b1x1, h1 = b1y2 - b1y1 + EPS_;
    float w2 = b2x2 - b2x1, h2 = b2y2 - b2y1 + EPS_;
    float uni = w1 * h1 + w2 * h2 - inter + EPS_;
    float iou = inter / uni;

    float cw = fmaxf(b1x2, b2x2) - fminf(b1x1, b2x1);
    float ch = fmaxf(b1y2, b2y2) - fminf(b1y1, b2y1);
    float c2 = cw * cw + ch * ch + EPS_;

    float dx = (b2x1 + b2x2 - b1x1 - b1x2);
    float dy = (b2y1 + b2y2 - b1y1 - b1y2);
    float rho2 = (dx * dx + dy * dy) * 0.25f;

    float dv = atanf(w2 / h2) - atanf(w1 / h1);
    float v = (4.0f / (float)(M_PI * M_PI)) * dv * dv;
    float alpha = v / (v - iou + (1.0f + EPS_));

    return iou - (rho2 / c2 + v * alpha);
}

// ---------------- main kernel: passA + weighted obj softplus sweep ----------------
__global__ void __launch_bounds__(256)
k_main(const float* __restrict__ p0,
       const float* __restrict__ p1,
       const float* __restrict__ p2,
       const float* __restrict__ tg,
       const float* __restrict__ anc,
       int nt, int bs, int BA, int BOBJ) {
    int M = NA_ * nt;
    int Elvl = 5 * M;
    int Etot = 3 * Elvl;

    int c0 = bs * NA_ * 6400;
    int c1 = bs * NA_ * 1600;
    int c2 = bs * NA_ * 400;
    float w0 = 1.0f / (float)c0;
    float w1 = 1.0f / (float)c1;
    float w2 = 1.0f / (float)c2;

    if ((int)blockIdx.x < BA) {
        // ---------------- passA: one warp per candidate entry ----------------
        // Block-level accumulators (per level): box, cls, corr (float), nv (int)
        __shared__ float s_box[3], s_cls[3], s_corr;
        __shared__ int   s_nv[3];
        int tid = threadIdx.x;
        if (tid < 3) { s_box[tid] = 0.0f; s_cls[tid] = 0.0f; s_nv[tid] = 0; }
        if (tid == 0) s_corr = 0.0f;
        __syncthreads();

        int warp = (blockIdx.x * blockDim.x + tid) >> 5;
        int lane = tid & 31;

        bool active = (warp < Etot);
        int lvl = 0;
        if (active) {
            lvl = warp / Elvl;
            int ein = warp - lvl * Elvl;
            int o = ein / M;
            int m = ein - o * M;
            int a = m / nt;
            int n = m - a * nt;

            int H = 80 >> lvl;
            int W = H;
            const float* pi = (lvl == 0) ? p0 : ((lvl == 1) ? p1 : p2);
            int woff = (lvl == 0) ? 0 : ((lvl == 1) ? c0 : c0 + c1);
            float wlvl = (lvl == 0) ? w0 : ((lvl == 1) ? w1 : w2);

            float gx = tg[n * 6 + 2] * (float)W;
            float gy = tg[n * 6 + 3] * (float)H;
            float gw = tg[n * 6 + 4] * (float)W;
            float gh = tg[n * 6 + 5] * (float)H;

            float aw = anc[(lvl * NA_ + a) * 2 + 0];
            float ah = anc[(lvl * NA_ + a) * 2 + 1];

            float rw = gw / aw, rh = gh / ah;
            float mr = fmaxf(fmaxf(rw, 1.0f / rw), fmaxf(rh, 1.0f / rh));
            bool m0 = mr < 4.0f;

            bool jmo;
            float offx = 0.0f, offy = 0.0f;
            switch (o) {
                case 0: jmo = true; break;
                case 1: jmo = ((gx - truncf(gx)) < 0.5f) && (gx > 1.0f); offx = 0.5f; break;
                case 2: jmo = ((gy - truncf(gy)) < 0.5f) && (gy > 1.0f); offy = 0.5f; break;
                case 3: { float gxi = (float)W - gx;
                          jmo = ((gxi - truncf(gxi)) < 0.5f) && (gxi > 1.0f); offx = -0.5f; } break;
                default:{ float gyi = (float)H - gy;
                          jmo = ((gyi - truncf(gyi)) < 0.5f) && (gyi > 1.0f); offy = -0.5f; } break;
            }

            if (jmo && m0) {   // warp-uniform
                int b = (int)tg[n * 6 + 0];
                int c = (int)tg[n * 6 + 1];

                int gi = (int)truncf(gx - offx); gi = min(max(gi, 0), W - 1);
                int gj = (int)truncf(gy - offy); gj = min(max(gj, 0), H - 1);

                const float* row = pi + (size_t)((((b * NA_ + a) * H + gj) * W + gi)) * CH_;

                float csum = 0.0f;
                #pragma unroll
                for (int it = 0; it < 3; it++) {
                    int j = lane + it * 32;
                    if (j < NC_) {
                        float x = row[5 + j];
                        float y = (j == c) ? 1.0f : 0.0f;
                        csum += fmaxf(x, 0.0f) - x * y + log1pf(__expf(-fabsf(x)));
                    }
                }
                #pragma unroll
                for (int s = 16; s; s >>= 1)
                    csum += __shfl_down_sync(0xffffffffu, csum, s);

                if (lane == 0) {
                    float q0 = row[0], q1 = row[1], q2 = row[2], q3 = row[3], q4 = row[4];
                    float px = sigmoidf_(q0) * 2.0f - 0.5f;
                    float py = sigmoidf_(q1) * 2.0f - 0.5f;
                    float sw = sigmoidf_(q2) * 2.0f;  float pw = sw * sw * aw;
                    float shh = sigmoidf_(q3) * 2.0f; float ph = shh * shh * ah;

                    float tbx = gx - (float)gi;
                    float tby = gy - (float)gj;

                    float iou = ciou_(px, py, pw, ph, tbx, tby, gw, gh);

                    // block-local accumulation (shared atomics)
                    atomicAdd(&s_box[lvl], 1.0f - iou);
                    atomicAdd(&s_cls[lvl], csum);
                    atomicAdd(&s_nv[lvl], 1);

                    // compensated winner update
                    int cell = woff + (((b * NA_ + a) * H + gj) * W + gi);
                    unsigned int ep = g_epoch;
                    float payload = wlvl * q4 * fmaxf(iou, 0.0f);
                    unsigned long long tag =
                        ((unsigned long long)ep << 47) |
                        ((unsigned long long)((warp - lvl * Elvl) + 1) << 32) |
                        (unsigned long long)__float_as_uint(payload);
                    unsigned long long old = atomicMax(&g_winner[cell], tag);
                    if (tag > old) {
                        float prev = ((unsigned int)(old >> 47) == ep)
                                   ? __uint_as_float((unsigned int)old) : 0.0f;
                        atomicAdd(&s_corr, payload - prev);
                    }
                }
            }
        }

        __syncthreads();
        // one global atomic per nonzero scalar per block
        if (tid < 3) {
            if (s_nv[tid] != 0) {
                atomicAdd(&g_box[tid], s_box[tid]);
                atomicAdd(&g_cls[tid], s_cls[tid]);
                atomicAdd(&g_nv[tid], s_nv[tid]);
            }
        }
        if (tid == 3 && s_corr != 0.0f) atomicAdd(&g_corr, s_corr);
    } else {
        // ---------------- weighted objectness softplus sweep ----------------
        __shared__ float sh[256];
        int bid = blockIdx.x - BA;
        int tid = threadIdx.x;
        int total = c0 + c1 + c2;

        float s = 0.0f;
        for (int i = bid * blockDim.x + tid; i < total; i += BOBJ * blockDim.x) {
            const float* pi; int local; float w;
            if (i < c0)            { pi = p0; local = i;            w = w0; }
            else if (i < c0 + c1)  { pi = p1; local = i - c0;       w = w1; }
            else                   { pi = p2; local = i - c0 - c1;  w = w2; }
            s += w * softplus_bce0(pi[(size_t)local * CH_ + 4]);
        }
        sh[tid] = s;
        __syncthreads();
        for (int st = 128; st; st >>= 1) {
            if (tid < st) sh[tid] += sh[tid + st];
            __syncthreads();
        }
        if (tid == 0) atomicAdd(&g_sp, sh[0]);
    }
}

// ---------------- finalize: 32 threads, parallel scalar loads ----------------
__global__ void k_fin(float* __restrict__ out, int bs) {
    __shared__ float sv[16];
    int tid = threadIdx.x;

    // parallel loads: 0-2 box, 3-5 cls, 6-8 nv, 9 sp, 10 corr
    if (tid < 3)       { sv[tid]     = g_box[tid];          g_box[tid] = 0.0f; }
    else if (tid < 6)  { sv[tid]     = g_cls[tid - 3];      g_cls[tid - 3] = 0.0f; }
    else if (tid < 9)  { sv[tid]     = (float)g_nv[tid - 6]; g_nv[tid - 6] = 0; }
    else if (tid == 9) { sv[9]       = g_sp;                g_sp = 0.0f; }
    else if (tid == 10){ sv[10]      = g_corr;              g_corr = 0.0f; }
    __syncwarp();

    if (tid == 0) {
        float lbox = 0.0f, lcls = 0.0f;
        #pragma unroll
        for (int i = 0; i < 3; i++) {
            float nv = fmaxf(sv[6 + i], 1.0f);
            lbox += sv[i] / nv;
            lcls += sv[3 + i] / (nv * (float)NC_);
        }
        float lobj = sv[9] - sv[10];
        lbox *= 0.05f;   // BOX_GAIN
        lcls *= 0.5f;    // CLS_GAIN
        float loss = (lbox + lobj + lcls) * (float)bs;
        out[0] = loss;
        out[1] = lbox;
        out[2] = lobj;
        out[3] = lcls;
        g_epoch = g_epoch + 1u;   // invalidate this call's winner tags
    }
}

// ---------------- launch ----------------
extern "C" void kernel_launch(void* const* d_in, const int* in_sizes, int n_in,
                              void* d_out, int out_size) {
    const float* p0  = (const float*)d_in[0];
    const float* p1  = (const float*)d_in[1];
    const float* p2  = (const float*)d_in[2];
    const float* tg  = (const float*)d_in[3];
    const float* anc = (const float*)d_in[4];
    float* out = (float*)d_out;

    int bs = in_sizes[0] / (NA_ * 80 * 80 * CH_);
    int nt = in_sizes[3] / 6;

    int Etot = 3 * 5 * NA_ * nt;
    int BA = (Etot * 32 + 255) / 256;   // warp-per-entry blocks
    int BOBJ = 512;                     // obj sweep blocks

    k_main<<<BA + BOBJ, 256>>>(p0, p1, p2, tg, anc, nt, bs, BA, BOBJ);
    k_fin<<<1, 32>>>(out, bs);
}